// round 9
// baseline (speedup 1.0000x reference)
#include <cuda_runtime.h>
#include <cuda_fp16.h>
#include <cstdint>

// ============================================================================
// LSTMCell for GB300 — sm_103 (non-'a') path: fp16 mma.sync + cp.async.bulk.
//
//   Single GEMM kernel with JIT fp32->fp16 conversion folded in:
//   warp 7 of each CTA claims (atomicCAS) and converts upcoming A/B k-chunks
//   into the swizzled fp16 scratch, publishing via release-flags; the TMA
//   producer polls flags (acquire) before each bulk copy.  Conversion traffic
//   (288 MB) hides under the tensor-bound mainloop (DRAM was 5% busy).
//   Mainloop for warps 0-6 identical to the proven R5/R8 structure.
// ============================================================================

#define DINLINE __device__ __forceinline__

__device__ __align__(1024) __half g_Ah[4096UL * 4096];   // 32 MB
__device__ __align__(1024) __half g_Bh[8192UL * 4096];   // 64 MB
__device__ int g_flags[8192];   // A: [mt*64+kc] (0..2047), B: 2048+[nt*64+kc]

// ------------------------------- helpers -----------------------------------
DINLINE uint32_t smem_u32(const void* p) {
    uint32_t a;
    asm("{ .reg .u64 t; cvta.to.shared.u64 t, %1; cvt.u32.u64 %0, t; }"
        : "=r"(a) : "l"(p));
    return a;
}

DINLINE void mbar_init(uint32_t a, uint32_t cnt) {
    asm volatile("mbarrier.init.shared.b64 [%0], %1;" :: "r"(a), "r"(cnt) : "memory");
}
DINLINE void mbar_expect(uint32_t a, uint32_t tx) {
    asm volatile("mbarrier.arrive.expect_tx.shared.b64 _, [%0], %1;"
                 :: "r"(a), "r"(tx) : "memory");
}
DINLINE void mbar_arrive(uint32_t a) {
    asm volatile("mbarrier.arrive.shared.b64 _, [%0];" :: "r"(a) : "memory");
}
DINLINE void mbar_wait(uint32_t mbar, uint32_t parity) {
    uint32_t done;
    asm volatile(
        "{\n .reg .pred p;\n"
        " mbarrier.try_wait.parity.acquire.cta.shared::cta.b64 p, [%1], %2;\n"
        " selp.b32 %0, 1, 0, p;\n}"
        : "=r"(done) : "r"(mbar), "r"(parity) : "memory");
    if (!done) {
        asm volatile(
            "{\n .reg .pred P1;\n"
            "WL%=:\n"
            " mbarrier.try_wait.parity.acquire.cta.shared::cta.b64 P1, [%0], %1, 0x989680;\n"
            " @P1 bra.uni WD%=;\n"
            " bra.uni WL%=;\n"
            "WD%=:\n}"
            :: "r"(mbar), "r"(parity) : "memory");
    }
}

DINLINE void bulk_g2s(uint32_t dst, const void* src, uint32_t bytes, uint32_t mbar) {
    asm volatile(
        "cp.async.bulk.shared::cluster.global.mbarrier::complete_tx::bytes [%0], [%1], %2, [%3];"
        :: "r"(dst), "l"(src), "r"(bytes), "r"(mbar) : "memory");
}

// fast-math gates (ex2/rcp approx; errors ~1e-7, negligible vs fp16 inputs)
DINLINE float ex2a(float x) { float y; asm("ex2.approx.f32 %0, %1;" : "=f"(y) : "f"(x)); return y; }
DINLINE float rcpa(float x) { float y; asm("rcp.approx.f32 %0, %1;" : "=f"(y) : "f"(x)); return y; }
DINLINE float sigf(float x)  { return rcpa(1.0f + ex2a(-1.442695041f * x)); }
DINLINE float tanhp(float x) { return 2.0f * sigf(2.0f * x) - 1.0f; }

// ------------------------ JIT conversion machinery -------------------------
// chunk id bits (within one operand buffer): [c:3][m:7][kc:6][tile:rest]
// dst byte = (t>>3)*128 + ((c ^ (m&7)) << 4)   (SW128 swizzle, 16B granules)
DINLINE void chunk_store(__half* dstbuf, uint32_t t,
                         const float4& v0, const float4& v1)
{
    __half2 h0 = __floats2half2_rn(v0.x, v0.y);
    __half2 h1 = __floats2half2_rn(v0.z, v0.w);
    __half2 h2 = __floats2half2_rn(v1.x, v1.y);
    __half2 h3 = __floats2half2_rn(v1.z, v1.w);
    uint4 out;
    out.x = *reinterpret_cast<uint32_t*>(&h0);
    out.y = *reinterpret_cast<uint32_t*>(&h1);
    out.z = *reinterpret_cast<uint32_t*>(&h2);
    out.w = *reinterpret_cast<uint32_t*>(&h3);
    const uint32_t c = t & 7u, m = (t >> 3) & 127u;
    *reinterpret_cast<uint4*>((unsigned char*)dstbuf +
        ((size_t)(t >> 3) << 7) + ((c ^ (m & 7u)) << 4)) = out;
}

DINLINE void flag_release(int* f) {
    __threadfence();
    __syncwarp();
    if ((threadIdx.x & 31) == 0)
        asm volatile("st.release.gpu.global.u32 [%0], %1;" :: "l"(f), "r"(2) : "memory");
}

DINLINE void poll_flag(int* f) {
    int v;
    do {
        asm volatile("ld.acquire.gpu.global.u32 %0, [%1];" : "=r"(v) : "l"(f) : "memory");
    } while (v != 2);
}

// Convert one A chunk (mt, kc): 128 rows x 64 halves from x|h into g_Ah.
// Executed by one full warp.  lane handles m = lane + {0,32,64,96}, c = 0..7.
DINLINE void convert_A(const float* __restrict__ x, const float* __restrict__ h,
                       int mt, int kc, int lane)
{
    const float* srcbase = (kc < 32) ? x : h;
    const int kcol = (kc & 31) * 64;
    #pragma unroll
    for (int r = 0; r < 4; r++) {
        const int m = lane + r * 32;
        const float* src = srcbase + (size_t)(mt * 128 + m) * 2048 + kcol;
        #pragma unroll 2
        for (int c = 0; c < 8; c++) {
            float4 a = *reinterpret_cast<const float4*>(src + c * 8);
            float4 b = *reinterpret_cast<const float4*>(src + c * 8 + 4);
            uint32_t t = (uint32_t)c + (uint32_t)m * 8u + (uint32_t)kc * 1024u
                       + (uint32_t)mt * 65536u;
            chunk_store(g_Ah, t, a, b);
        }
    }
}

// Convert one B chunk (nt, kc): 128 packed-n rows x 64 halves from wi|wh.
// packed row m -> source row (m>>5)*2048 + nt*32 + (m&31)  (gate interleave)
DINLINE void convert_B(const float* __restrict__ wi, const float* __restrict__ wh,
                       int nt, int kc, int lane)
{
    const float* srcbase = (kc < 32) ? wi : wh;
    const int kcol = (kc & 31) * 64;
    #pragma unroll
    for (int r = 0; r < 4; r++) {
        const int m = lane + r * 32;
        const int srow = ((m >> 5) << 11) + nt * 32 + (m & 31);
        const float* src = srcbase + (size_t)srow * 2048 + kcol;
        #pragma unroll 2
        for (int c = 0; c < 8; c++) {
            float4 a = *reinterpret_cast<const float4*>(src + c * 8);
            float4 b = *reinterpret_cast<const float4*>(src + c * 8 + 4);
            uint32_t t = (uint32_t)c + (uint32_t)m * 8u + (uint32_t)kc * 1024u
                       + (uint32_t)nt * 65536u;
            chunk_store(g_Bh, t, a, b);
        }
    }
}

// Full-warp claim + convert for chunk kc of this CTA's (mt, nt).
DINLINE void claim_convert(const float* x, const float* h,
                           const float* wi, const float* wh,
                           int mt, int nt, int kc, int lane)
{
    int* fA = &g_flags[mt * 64 + kc];
    int* fB = &g_flags[2048 + nt * 64 + kc];
    int oldA = 0, oldB = 0;
    if (lane == 0) {
        oldA = atomicCAS(fA, 0, 1);
        oldB = atomicCAS(fB, 0, 1);
    }
    oldA = __shfl_sync(0xFFFFFFFFu, oldA, 0);
    oldB = __shfl_sync(0xFFFFFFFFu, oldB, 0);
    if (oldA == 0) { convert_A(x, h, mt, kc, lane); flag_release(fA); }
    if (oldB == 0) { convert_B(wi, wh, nt, kc, lane); flag_release(fB); }
}

__global__ void clear_flags()
{
    g_flags[blockIdx.x * 256 + threadIdx.x] = 0;
}

// ============================================================================
// Fused GEMM + LSTM cell (+ JIT conversion).
//   CTA tile 128(M) x 128(packed N = 4 gates x 32 h-cols), BK=64.
//   8 warps 2(M) x 4(N); warp tile 64x32; mma m16n8k16 fp16->fp32.
//   Pipeline: full[s] (tx mbarrier) + empty[s] (count-8, per-warp arrive).
// ============================================================================
static constexpr int TILE_BYTES  = 16384;                 // 128 x 128B
static constexpr int STAGE_BYTES = 2 * TILE_BYTES;        // A + B
static constexpr int STAGES      = 3;
static constexpr int KITERS      = 64;                    // 4096 / 64
static constexpr int CLAIM_AHEAD = 6;                     // claim lead (iters)
static constexpr int SMEM_ALLOC  = STAGES * STAGE_BYTES + 1024;

__global__ __launch_bounds__(256, 2)
void lstm_gemm(const float* __restrict__ x,  const float* __restrict__ hin,
               const float* __restrict__ wi, const float* __restrict__ wh,
               const float* __restrict__ Bv, const float* __restrict__ Cin,
               float* __restrict__ Oh, float* __restrict__ Oc, float* __restrict__ Og)
{
    extern __shared__ unsigned char smraw[];
    __shared__ __align__(8) unsigned long long mbar_s[2 * STAGES];  // full[3], empty[3]
    __shared__ float s_bias[128];

    const int tid  = threadIdx.x;
    const int lane = tid & 31;
    const int w    = tid >> 5;
    const int wm   = w & 1;        // 0..1  (M)
    const int wn   = w >> 1;       // 0..3  (N)
    const int mtile = blockIdx.x & 31;   // 0..31
    const int ntile = blockIdx.x >> 5;   // 0..63 (h-col block of 32)

    const uint32_t smb = (smem_u32(smraw) + 1023u) & ~1023u;
    unsigned char* smal = smraw + (smb - smem_u32(smraw));
    const uint32_t mbb = smem_u32(&mbar_s[0]);     // full[s]  at mbb + s*8
    const uint32_t ebb = mbb + STAGES * 8;         // empty[s] at ebb + s*8

    if (tid == 0) {
        #pragma unroll
        for (int s = 0; s < STAGES; s++) {
            mbar_init(mbb + s * 8, 1);
            mbar_init(ebb + s * 8, 8);             // one arrive per warp
        }
    }
    if (tid < 128)
        s_bias[tid] = Bv[(size_t)((tid >> 5) << 11) + (size_t)ntile * 32 + (tid & 31)];
    __syncthreads();

    // ---- JIT prologue: warp 7 claims/converts chunks 0..CLAIM_AHEAD-1 ----
    if (w == 7) {
        #pragma unroll 1
        for (int kc = 0; kc < CLAIM_AHEAD; kc++)
            claim_convert(x, hin, wi, wh, mtile, ntile, kc, lane);
    }

    const uint64_t gA = (uint64_t)(const void*)g_Ah + (uint64_t)(mtile * 64) * TILE_BYTES;
    const uint64_t gB = (uint64_t)(const void*)g_Bh + (uint64_t)(ntile * 64) * TILE_BYTES;

    auto produce = [&](int it, int s) {
        const uint32_t mb = mbb + s * 8;
        mbar_expect(mb, (uint32_t)STAGE_BYTES);
        bulk_g2s(smb + s * STAGE_BYTES,
                 (const void*)(gA + (uint64_t)it * TILE_BYTES), TILE_BYTES, mb);
        bulk_g2s(smb + s * STAGE_BYTES + TILE_BYTES,
                 (const void*)(gB + (uint64_t)it * TILE_BYTES), TILE_BYTES, mb);
    };
    if (tid == 0) {
        #pragma unroll 1
        for (int s = 0; s < STAGES; s++) {
            poll_flag(&g_flags[mtile * 64 + s]);
            poll_flag(&g_flags[2048 + ntile * 64 + s]);
            produce(s, s);
        }
    }

    // fragment address components (byte offsets inside a 16KB tile)
    uint32_t arow[4], brow4[2], cxA[4], cxB[4];
    #pragma unroll
    for (int mi = 0; mi < 4; mi++)
        arow[mi] = (uint32_t)((wm * 64 + mi * 16 + ((lane >> 3) & 1) * 8 + (lane & 7)) << 7);
    #pragma unroll
    for (int p = 0; p < 2; p++)   // ldmatrix.x4 covering n-frag pair (2p, 2p+1)
        brow4[p] = (uint32_t)(TILE_BYTES +
                   ((wn * 32 + p * 16 + ((lane >> 4) & 1) * 8 + (lane & 7)) << 7));
    #pragma unroll
    for (int ks = 0; ks < 4; ks++) {
        cxA[ks] = (uint32_t)((((2 * ks + (lane >> 4)) ^ (lane & 7)) << 4));
        cxB[ks] = (uint32_t)((((2 * ks + ((lane >> 3) & 1)) ^ (lane & 7)) << 4));
    }

    float acc[4][4][4];
    #pragma unroll
    for (int mi = 0; mi < 4; mi++)
        #pragma unroll
        for (int ni = 0; ni < 4; ni++)
            #pragma unroll
            for (int r = 0; r < 4; r++) acc[mi][ni][r] = 0.0f;

    // ring state: parity for stage st at iteration it is (it / STAGES) & 1
    int st = 0;
    uint32_t trip = 0;

    for (int it = 0; it < KITERS; it++) {
        // ---- JIT: warp 7 claims/converts chunk it+CLAIM_AHEAD ----
        if (w == 7 && it + CLAIM_AHEAD < KITERS)
            claim_convert(x, hin, wi, wh, mtile, ntile, it + CLAIM_AHEAD, lane);

        const uint32_t par = trip & 1u;
        mbar_wait(mbb + st * 8, par);
        const uint32_t base = smb + st * STAGE_BYTES;

        #pragma unroll
        for (int ks = 0; ks < 4; ks++) {
            uint32_t b0[4], b1[4];
            #pragma unroll
            for (int p = 0; p < 2; p++)
                asm volatile("ldmatrix.sync.aligned.m8n8.x4.shared.b16 {%0,%1,%2,%3}, [%4];"
                             : "=r"(b0[2*p]), "=r"(b1[2*p]), "=r"(b0[2*p+1]), "=r"(b1[2*p+1])
                             : "r"(base + brow4[p] + cxB[ks]));
            #pragma unroll
            for (int mi = 0; mi < 4; mi++) {
                uint32_t a0, a1, a2, a3;
                asm volatile("ldmatrix.sync.aligned.m8n8.x4.shared.b16 {%0,%1,%2,%3}, [%4];"
                             : "=r"(a0), "=r"(a1), "=r"(a2), "=r"(a3)
                             : "r"(base + arow[mi] + cxA[ks]));
                #pragma unroll
                for (int ni = 0; ni < 4; ni++)
                    asm volatile(
                        "mma.sync.aligned.m16n8k16.row.col.f32.f16.f16.f32 "
                        "{%0,%1,%2,%3}, {%4,%5,%6,%7}, {%8,%9}, {%0,%1,%2,%3};"
                        : "+f"(acc[mi][ni][0]), "+f"(acc[mi][ni][1]),
                          "+f"(acc[mi][ni][2]), "+f"(acc[mi][ni][3])
                        : "r"(a0), "r"(a1), "r"(a2), "r"(a3),
                          "r"(b0[ni]), "r"(b1[ni]));
            }
        }

        // warp done reading stage st (warp-collective ops => whole warp done)
        if (lane == 0) mbar_arrive(ebb + st * 8);

        // producer: refill st for iteration it+STAGES once all warps arrived
        if (tid == 0 && it + STAGES < KITERS) {
            poll_flag(&g_flags[mtile * 64 + it + STAGES]);
            poll_flag(&g_flags[2048 + ntile * 64 + it + STAGES]);
            mbar_wait(ebb + st * 8, trip & 1u);
            produce(it + STAGES, st);
        }

        if (++st == STAGES) { st = 0; trip++; }
    }

    // ------------- fused epilogue: acc -> SMEM -> gates -> outputs ---------
    __syncthreads();                               // pipeline fully drained
    float* sC = reinterpret_cast<float*>(smal);    // [128][132] fp32

    const size_t mbase = (size_t)mtile * 128;
    const size_t hb    = (size_t)ntile * 32;

    // prefetch Cin (overlaps with acc->SMEM transpose + barrier)
    float cin[16];
    #pragma unroll
    for (int kk = 0; kk < 16; kk++) {
        const int idx = kk * 256 + tid;
        const int m = idx >> 5, cc = idx & 31;
        cin[kk] = Cin[(mbase + m) * 2048 + hb + cc];
    }

    #pragma unroll
    for (int mi = 0; mi < 4; mi++) {
        const int r0 = wm * 64 + mi * 16 + (lane >> 2);
        #pragma unroll
        for (int ni = 0; ni < 4; ni++) {
            const int c0 = wn * 32 + ni * 8 + (lane & 3) * 2;
            *reinterpret_cast<float2*>(&sC[r0 * 132 + c0]) =
                make_float2(acc[mi][ni][0], acc[mi][ni][1]);
            *reinterpret_cast<float2*>(&sC[(r0 + 8) * 132 + c0]) =
                make_float2(acc[mi][ni][2], acc[mi][ni][3]);
        }
    }
    __syncthreads();

    #pragma unroll
    for (int kk = 0; kk < 16; kk++) {
        const int idx = kk * 256 + tid;
        const int m = idx >> 5, cc = idx & 31;
        const float gf = sC[m * 132 +       cc] + s_bias[cc];
        const float gi = sC[m * 132 +  32 + cc] + s_bias[32 + cc];
        const float gs = sC[m * 132 +  64 + cc] + s_bias[64 + cc];
        const float gg = sC[m * 132 +  96 + cc] + s_bias[96 + cc];

        const float f  = sigf(gf);
        const float ii = sigf(gi);
        const float ss = tanhp(gs);
        const float oo = sigf(gg);
        const float cn = f * cin[kk] + ii * ss;
        const float hn = oo * tanhp(cn);

        const size_t off = (mbase + m) * 2048 + hb + cc;
        Oh[off] = hn;
        Oc[off] = cn;
        Og[off] = oo;
    }
}

// ============================================================================
// launch
// ============================================================================
extern "C" void kernel_launch(void* const* d_in, const int* in_sizes, int n_in,
                              void* d_out, int out_size)
{
    const float* x    = (const float*)d_in[0];
    const float* h    = (const float*)d_in[1];
    const float* c    = (const float*)d_in[2];
    /* d_in[3] = o, unused by the reference computation */
    const float* w_ih = (const float*)d_in[4];
    const float* w_hh = (const float*)d_in[5];
    const float* b    = (const float*)d_in[6];
    float* out = (float*)d_out;

    cudaFuncSetAttribute(lstm_gemm,
                         cudaFuncAttributeMaxDynamicSharedMemorySize, SMEM_ALLOC);

    clear_flags<<<32, 256>>>();

    float* out_h  = out;
    float* out_c  = out + (size_t)4096 * 2048;
    float* out_go = out + (size_t)2 * 4096 * 2048;
    lstm_gemm<<<2048, 256, SMEM_ALLOC>>>(x, h, w_ih, w_hh, b, c,
                                         out_h, out_c, out_go);
}

// round 10
// speedup vs baseline: 1.7484x; 1.7484x over previous
#include <cuda_runtime.h>
#include <cuda_fp16.h>
#include <cstdint>

// ============================================================================
// LSTMCell for GB300 — sm_103 (non-'a') path: fp16 mma.sync + cp.async.bulk.
//
//   Pass 1: fp32 -> fp16 (RN), pre-tiled + SW128-swizzled, MLP=8 loads.
//   Pass 2: GEMM 128x128x(BK=64), 3-stage bulk-copy mbarrier ring with
//           trip-level unroll (compile-time stage offsets/parities),
//           fused fast-math LSTM epilogue with Cin prefetch.
// ============================================================================

#define DINLINE __device__ __forceinline__

__device__ __align__(1024) __half g_Ah[4096UL * 4096];   // 32 MB
__device__ __align__(1024) __half g_Bh[8192UL * 4096];   // 64 MB

// ------------------------------- helpers -----------------------------------
DINLINE uint32_t smem_u32(const void* p) {
    uint32_t a;
    asm("{ .reg .u64 t; cvta.to.shared.u64 t, %1; cvt.u32.u64 %0, t; }"
        : "=r"(a) : "l"(p));
    return a;
}

DINLINE void mbar_init(uint32_t a, uint32_t cnt) {
    asm volatile("mbarrier.init.shared.b64 [%0], %1;" :: "r"(a), "r"(cnt) : "memory");
}
DINLINE void mbar_expect(uint32_t a, uint32_t tx) {
    asm volatile("mbarrier.arrive.expect_tx.shared.b64 _, [%0], %1;"
                 :: "r"(a), "r"(tx) : "memory");
}
DINLINE void mbar_arrive(uint32_t a) {
    asm volatile("mbarrier.arrive.shared.b64 _, [%0];" :: "r"(a) : "memory");
}
DINLINE void mbar_wait(uint32_t mbar, uint32_t parity) {
    uint32_t done;
    asm volatile(
        "{\n .reg .pred p;\n"
        " mbarrier.try_wait.parity.acquire.cta.shared::cta.b64 p, [%1], %2;\n"
        " selp.b32 %0, 1, 0, p;\n}"
        : "=r"(done) : "r"(mbar), "r"(parity) : "memory");
    if (!done) {
        asm volatile(
            "{\n .reg .pred P1;\n"
            "WL%=:\n"
            " mbarrier.try_wait.parity.acquire.cta.shared::cta.b64 P1, [%0], %1, 0x989680;\n"
            " @P1 bra.uni WD%=;\n"
            " bra.uni WL%=;\n"
            "WD%=:\n}"
            :: "r"(mbar), "r"(parity) : "memory");
    }
}

DINLINE void bulk_g2s(uint32_t dst, const void* src, uint32_t bytes, uint32_t mbar) {
    asm volatile(
        "cp.async.bulk.shared::cluster.global.mbarrier::complete_tx::bytes [%0], [%1], %2, [%3];"
        :: "r"(dst), "l"(src), "r"(bytes), "r"(mbar) : "memory");
}

// fast-math gates (ex2/rcp approx; errors ~1e-7, negligible vs fp16 inputs)
DINLINE float ex2a(float x) { float y; asm("ex2.approx.f32 %0, %1;" : "=f"(y) : "f"(x)); return y; }
DINLINE float rcpa(float x) { float y; asm("rcp.approx.f32 %0, %1;" : "=f"(y) : "f"(x)); return y; }
DINLINE float sigf(float x)  { return rcpa(1.0f + ex2a(-1.442695041f * x)); }
DINLINE float tanhp(float x) { return 2.0f * sigf(2.0f * x) - 1.0f; }

// ============================================================================
// Pass 1: convert + tile + swizzle.  Chunk = 16B of fp16 (8 halves).
//   chunk id bits: [c:3][m:7][kc:6][tile:rest]
//   4 chunks per thread, all 8 LDG.128 issued before converts (MLP=8).
// ============================================================================
DINLINE const float* chunk_src(const float* a, const float* b,
                               uint32_t t, int which)
{
    const uint32_t c = t & 7u;
    const uint32_t m = (t >> 3) & 127u;
    const uint32_t k = ((t >> 10) & 63u) * 64u + c * 8u;
    const uint32_t tile = t >> 16;
    uint32_t src_row;
    if (which) src_row = ((m >> 5) << 11) + tile * 32u + (m & 31u);
    else       src_row = tile * 128u + m;
    const size_t srow = (size_t)src_row * 2048;
    return (k < 2048u) ? (a + srow + k) : (b + srow + (k - 2048u));
}

DINLINE void chunk_store(__half* dstbuf, uint32_t t,
                         const float4& v0, const float4& v1)
{
    __half2 h0 = __floats2half2_rn(v0.x, v0.y);
    __half2 h1 = __floats2half2_rn(v0.z, v0.w);
    __half2 h2 = __floats2half2_rn(v1.x, v1.y);
    __half2 h3 = __floats2half2_rn(v1.z, v1.w);
    uint4 out;
    out.x = *reinterpret_cast<uint32_t*>(&h0);
    out.y = *reinterpret_cast<uint32_t*>(&h1);
    out.z = *reinterpret_cast<uint32_t*>(&h2);
    out.w = *reinterpret_cast<uint32_t*>(&h3);
    const uint32_t c = t & 7u, m = (t >> 3) & 127u;
    *reinterpret_cast<uint4*>((unsigned char*)dstbuf +
        ((size_t)(t >> 3) << 7) + ((c ^ (m & 7u)) << 4)) = out;
}

__global__ __launch_bounds__(256)
void cvt_pack(const float* __restrict__ x,  const float* __restrict__ h,
              const float* __restrict__ wi, const float* __restrict__ wh)
{
    const uint32_t g = blockIdx.x * 256u + threadIdx.x;
    float4 v[8];
    uint32_t t[4];

    if (g < (1u << 19)) {
        #pragma unroll
        for (int j = 0; j < 4; j++) t[j] = g + (uint32_t)j * (1u << 19);
        #pragma unroll
        for (int j = 0; j < 4; j++) {
            const float* s = chunk_src(x, h, t[j], 0);
            v[2*j]   = *reinterpret_cast<const float4*>(s);
            v[2*j+1] = *reinterpret_cast<const float4*>(s + 4);
        }
        #pragma unroll
        for (int j = 0; j < 4; j++) chunk_store(g_Ah, t[j], v[2*j], v[2*j+1]);
    } else {
        const uint32_t q = g - (1u << 19);
        #pragma unroll
        for (int j = 0; j < 4; j++) t[j] = q + (uint32_t)j * (1u << 20);
        #pragma unroll
        for (int j = 0; j < 4; j++) {
            const float* s = chunk_src(wi, wh, t[j], 1);
            v[2*j]   = *reinterpret_cast<const float4*>(s);
            v[2*j+1] = *reinterpret_cast<const float4*>(s + 4);
        }
        #pragma unroll
        for (int j = 0; j < 4; j++) chunk_store(g_Bh, t[j], v[2*j], v[2*j+1]);
    }
}

// ============================================================================
// Pass 2: fused GEMM + LSTM cell.
//   CTA tile 128(M) x 128(packed N = 4 gates x 32 h-cols), BK=64.
//   8 warps 2(M) x 4(N); warp tile 64x32; mma m16n8k16 fp16->fp32.
//   Pipeline: full[s] (tx mbarrier) + empty[s] (count-8, per-warp arrive).
//   Mainloop unrolled by ring depth: stage offsets/parities compile-time.
// ============================================================================
static constexpr int TILE_BYTES  = 16384;                 // 128 x 128B
static constexpr int STAGE_BYTES = 2 * TILE_BYTES;        // A + B
static constexpr int STAGES      = 3;
static constexpr int KITERS      = 64;                    // 4096 / 64
static constexpr int SMEM_ALLOC  = STAGES * STAGE_BYTES + 1024;

__global__ __launch_bounds__(256, 2)
void lstm_gemm(const float* __restrict__ Bv, const float* __restrict__ Cin,
               float* __restrict__ Oh, float* __restrict__ Oc, float* __restrict__ Og)
{
    extern __shared__ unsigned char smraw[];
    __shared__ __align__(8) unsigned long long mbar_s[2 * STAGES];  // full[3], empty[3]
    __shared__ float s_bias[128];

    const int tid  = threadIdx.x;
    const int lane = tid & 31;
    const int w    = tid >> 5;
    const int wm   = w & 1;        // 0..1  (M)
    const int wn   = w >> 1;       // 0..3  (N)
    const int mtile = blockIdx.x & 31;   // 0..31
    const int ntile = blockIdx.x >> 5;   // 0..63 (h-col block of 32)

    const uint32_t smb = (smem_u32(smraw) + 1023u) & ~1023u;
    unsigned char* smal = smraw + (smb - smem_u32(smraw));
    const uint32_t mbb = smem_u32(&mbar_s[0]);     // full[s]  at mbb + s*8
    const uint32_t ebb = mbb + STAGES * 8;         // empty[s] at ebb + s*8

    if (tid == 0) {
        #pragma unroll
        for (int s = 0; s < STAGES; s++) {
            mbar_init(mbb + s * 8, 1);
            mbar_init(ebb + s * 8, 8);             // one arrive per warp
        }
    }
    if (tid < 128)
        s_bias[tid] = Bv[(size_t)((tid >> 5) << 11) + (size_t)ntile * 32 + (tid & 31)];
    __syncthreads();

    const uint64_t gA = (uint64_t)(const void*)g_Ah + (uint64_t)(mtile * 64) * TILE_BYTES;
    const uint64_t gB = (uint64_t)(const void*)g_Bh + (uint64_t)(ntile * 64) * TILE_BYTES;

    auto produce = [&](int it, int s) {
        const uint32_t mb = mbb + s * 8;
        mbar_expect(mb, (uint32_t)STAGE_BYTES);
        bulk_g2s(smb + s * STAGE_BYTES,
                 (const void*)(gA + (uint64_t)it * TILE_BYTES), TILE_BYTES, mb);
        bulk_g2s(smb + s * STAGE_BYTES + TILE_BYTES,
                 (const void*)(gB + (uint64_t)it * TILE_BYTES), TILE_BYTES, mb);
    };
    if (tid == 0) { produce(0, 0); produce(1, 1); produce(2, 2); }

    // fragment address components (byte offsets inside a 16KB tile)
    uint32_t arow[4], brow4[2], cxA[4], cxB[4];
    #pragma unroll
    for (int mi = 0; mi < 4; mi++)
        arow[mi] = (uint32_t)((wm * 64 + mi * 16 + ((lane >> 3) & 1) * 8 + (lane & 7)) << 7);
    #pragma unroll
    for (int p = 0; p < 2; p++)   // ldmatrix.x4 covering n-frag pair (2p, 2p+1)
        brow4[p] = (uint32_t)(TILE_BYTES +
                   ((wn * 32 + p * 16 + ((lane >> 4) & 1) * 8 + (lane & 7)) << 7));
    #pragma unroll
    for (int ks = 0; ks < 4; ks++) {
        cxA[ks] = (uint32_t)((((2 * ks + (lane >> 4)) ^ (lane & 7)) << 4));
        cxB[ks] = (uint32_t)((((2 * ks + ((lane >> 3) & 1)) ^ (lane & 7)) << 4));
    }

    float acc[4][4][4];
    #pragma unroll
    for (int mi = 0; mi < 4; mi++)
        #pragma unroll
        for (int ni = 0; ni < 4; ni++)
            #pragma unroll
            for (int r = 0; r < 4; r++) acc[mi][ni][r] = 0.0f;

    // one k-chunk consume: stage offsets are compile-time per call site
    auto consume = [&](uint32_t base) {
        #pragma unroll
        for (int ks = 0; ks < 4; ks++) {
            uint32_t b0[4], b1[4];
            #pragma unroll
            for (int p = 0; p < 2; p++)
                asm volatile("ldmatrix.sync.aligned.m8n8.x4.shared.b16 {%0,%1,%2,%3}, [%4];"
                             : "=r"(b0[2*p]), "=r"(b1[2*p]), "=r"(b0[2*p+1]), "=r"(b1[2*p+1])
                             : "r"(base + brow4[p] + cxB[ks]));
            #pragma unroll
            for (int mi = 0; mi < 4; mi++) {
                uint32_t a0, a1, a2, a3;
                asm volatile("ldmatrix.sync.aligned.m8n8.x4.shared.b16 {%0,%1,%2,%3}, [%4];"
                             : "=r"(a0), "=r"(a1), "=r"(a2), "=r"(a3)
                             : "r"(base + arow[mi] + cxA[ks]));
                #pragma unroll
                for (int ni = 0; ni < 4; ni++)
                    asm volatile(
                        "mma.sync.aligned.m16n8k16.row.col.f32.f16.f16.f32 "
                        "{%0,%1,%2,%3}, {%4,%5,%6,%7}, {%8,%9}, {%0,%1,%2,%3};"
                        : "+f"(acc[mi][ni][0]), "+f"(acc[mi][ni][1]),
                          "+f"(acc[mi][ni][2]), "+f"(acc[mi][ni][3])
                        : "r"(a0), "r"(a1), "r"(a2), "r"(a3),
                          "r"(b0[ni]), "r"(b1[ni]));
            }
        }
    };

    // ---- mainloop: 20 uniform trips of 3 (it 0..59), then 4-iter tail ----
    for (int trip = 0; trip < 20; trip++) {
        const uint32_t par = (uint32_t)trip & 1u;
        const int it0 = trip * 3;
        #pragma unroll
        for (int j = 0; j < STAGES; j++) {          // stage j == it % 3
            mbar_wait(mbb + j * 8, par);
            consume(smb + j * STAGE_BYTES);
            if (lane == 0) mbar_arrive(ebb + j * 8);
            if (tid == 0) {
                mbar_wait(ebb + j * 8, par);
                produce(it0 + j + STAGES, j);       // it+3 <= 62 always
            }
        }
    }
    // tail: it = 60 (st0,p0), 61 (st1,p0), 62 (st2,p0), 63 (st0,p1)
    {
        mbar_wait(mbb + 0, 0);
        consume(smb);
        if (lane == 0) mbar_arrive(ebb + 0);
        if (tid == 0) { mbar_wait(ebb + 0, 0); produce(63, 0); }

        mbar_wait(mbb + 8, 0);
        consume(smb + STAGE_BYTES);
        if (lane == 0) mbar_arrive(ebb + 8);

        mbar_wait(mbb + 16, 0);
        consume(smb + 2 * STAGE_BYTES);
        if (lane == 0) mbar_arrive(ebb + 16);

        mbar_wait(mbb + 0, 1);
        consume(smb);
    }

    // ------------- fused epilogue: acc -> SMEM -> gates -> outputs ---------
    __syncthreads();                               // pipeline fully drained
    float* sC = reinterpret_cast<float*>(smal);    // [128][132] fp32

    const size_t mbase = (size_t)mtile * 128;
    const size_t hb    = (size_t)ntile * 32;

    // prefetch Cin (overlaps with acc->SMEM transpose + barrier)
    float cin[16];
    #pragma unroll
    for (int kk = 0; kk < 16; kk++) {
        const int idx = kk * 256 + tid;
        const int m = idx >> 5, cc = idx & 31;
        cin[kk] = Cin[(mbase + m) * 2048 + hb + cc];
    }

    #pragma unroll
    for (int mi = 0; mi < 4; mi++) {
        const int r0 = wm * 64 + mi * 16 + (lane >> 2);
        #pragma unroll
        for (int ni = 0; ni < 4; ni++) {
            const int c0 = wn * 32 + ni * 8 + (lane & 3) * 2;
            *reinterpret_cast<float2*>(&sC[r0 * 132 + c0]) =
                make_float2(acc[mi][ni][0], acc[mi][ni][1]);
            *reinterpret_cast<float2*>(&sC[(r0 + 8) * 132 + c0]) =
                make_float2(acc[mi][ni][2], acc[mi][ni][3]);
        }
    }
    __syncthreads();

    #pragma unroll
    for (int kk = 0; kk < 16; kk++) {
        const int idx = kk * 256 + tid;
        const int m = idx >> 5, cc = idx & 31;
        const float gf = sC[m * 132 +       cc] + s_bias[cc];
        const float gi = sC[m * 132 +  32 + cc] + s_bias[32 + cc];
        const float gs = sC[m * 132 +  64 + cc] + s_bias[64 + cc];
        const float gg = sC[m * 132 +  96 + cc] + s_bias[96 + cc];

        const float f  = sigf(gf);
        const float ii = sigf(gi);
        const float ss = tanhp(gs);
        const float oo = sigf(gg);
        const float cn = f * cin[kk] + ii * ss;
        const float hn = oo * tanhp(cn);

        const size_t off = (mbase + m) * 2048 + hb + cc;
        Oh[off] = hn;
        Oc[off] = cn;
        Og[off] = oo;
    }
}

// ============================================================================
// launch
// ============================================================================
extern "C" void kernel_launch(void* const* d_in, const int* in_sizes, int n_in,
                              void* d_out, int out_size)
{
    const float* x    = (const float*)d_in[0];
    const float* h    = (const float*)d_in[1];
    const float* c    = (const float*)d_in[2];
    /* d_in[3] = o, unused by the reference computation */
    const float* w_ih = (const float*)d_in[4];
    const float* w_hh = (const float*)d_in[5];
    const float* b    = (const float*)d_in[6];
    float* out = (float*)d_out;

    cudaFuncSetAttribute(lstm_gemm,
                         cudaFuncAttributeMaxDynamicSharedMemorySize, SMEM_ALLOC);

    cvt_pack<<<6144, 256>>>(x, h, w_ih, w_hh);

    float* out_h  = out;
    float* out_c  = out + (size_t)4096 * 2048;
    float* out_go = out + (size_t)2 * 4096 * 2048;
    lstm_gemm<<<2048, 256, SMEM_ALLOC>>>(b, c, out_h, out_c, out_go);
}

// round 11
// speedup vs baseline: 1.7582x; 1.0056x over previous
#include <cuda_runtime.h>
#include <cuda_fp16.h>
#include <cstdint>

// ============================================================================
// LSTMCell for GB300 — sm_103 (non-'a') path: fp16 mma.sync + cp.async.bulk.
//
//   Pass 1: fp32 -> fp16 (RN), pre-tiled + SW128-swizzled, MLP=8 loads.
//   Pass 2: GEMM 128x128x(BK=64), 3-stage bulk-copy mbarrier ring with
//           trip-level unroll (compile-time stage offsets/parities) and
//           ROUND-ROBIN producer (stage j refilled by warp j, lane 0),
//           fused fast-math LSTM epilogue with Cin prefetch.
// ============================================================================

#define DINLINE __device__ __forceinline__

__device__ __align__(1024) __half g_Ah[4096UL * 4096];   // 32 MB
__device__ __align__(1024) __half g_Bh[8192UL * 4096];   // 64 MB

// ------------------------------- helpers -----------------------------------
DINLINE uint32_t smem_u32(const void* p) {
    uint32_t a;
    asm("{ .reg .u64 t; cvta.to.shared.u64 t, %1; cvt.u32.u64 %0, t; }"
        : "=r"(a) : "l"(p));
    return a;
}

DINLINE void mbar_init(uint32_t a, uint32_t cnt) {
    asm volatile("mbarrier.init.shared.b64 [%0], %1;" :: "r"(a), "r"(cnt) : "memory");
}
DINLINE void mbar_expect(uint32_t a, uint32_t tx) {
    asm volatile("mbarrier.arrive.expect_tx.shared.b64 _, [%0], %1;"
                 :: "r"(a), "r"(tx) : "memory");
}
DINLINE void mbar_arrive(uint32_t a) {
    asm volatile("mbarrier.arrive.shared.b64 _, [%0];" :: "r"(a) : "memory");
}
DINLINE void mbar_wait(uint32_t mbar, uint32_t parity) {
    uint32_t done;
    asm volatile(
        "{\n .reg .pred p;\n"
        " mbarrier.try_wait.parity.acquire.cta.shared::cta.b64 p, [%1], %2;\n"
        " selp.b32 %0, 1, 0, p;\n}"
        : "=r"(done) : "r"(mbar), "r"(parity) : "memory");
    if (!done) {
        asm volatile(
            "{\n .reg .pred P1;\n"
            "WL%=:\n"
            " mbarrier.try_wait.parity.acquire.cta.shared::cta.b64 P1, [%0], %1, 0x989680;\n"
            " @P1 bra.uni WD%=;\n"
            " bra.uni WL%=;\n"
            "WD%=:\n}"
            :: "r"(mbar), "r"(parity) : "memory");
    }
}

DINLINE void bulk_g2s(uint32_t dst, const void* src, uint32_t bytes, uint32_t mbar) {
    asm volatile(
        "cp.async.bulk.shared::cluster.global.mbarrier::complete_tx::bytes [%0], [%1], %2, [%3];"
        :: "r"(dst), "l"(src), "r"(bytes), "r"(mbar) : "memory");
}

// fast-math gates (ex2/rcp approx; errors ~1e-7, negligible vs fp16 inputs)
DINLINE float ex2a(float x) { float y; asm("ex2.approx.f32 %0, %1;" : "=f"(y) : "f"(x)); return y; }
DINLINE float rcpa(float x) { float y; asm("rcp.approx.f32 %0, %1;" : "=f"(y) : "f"(x)); return y; }
DINLINE float sigf(float x)  { return rcpa(1.0f + ex2a(-1.442695041f * x)); }
DINLINE float tanhp(float x) { return 2.0f * sigf(2.0f * x) - 1.0f; }

// ============================================================================
// Pass 1: convert + tile + swizzle.  Chunk = 16B of fp16 (8 halves).
//   chunk id bits: [c:3][m:7][kc:6][tile:rest]
//   4 chunks per thread, all 8 LDG.128 issued before converts (MLP=8).
// ============================================================================
DINLINE const float* chunk_src(const float* a, const float* b,
                               uint32_t t, int which)
{
    const uint32_t c = t & 7u;
    const uint32_t m = (t >> 3) & 127u;
    const uint32_t k = ((t >> 10) & 63u) * 64u + c * 8u;
    const uint32_t tile = t >> 16;
    uint32_t src_row;
    if (which) src_row = ((m >> 5) << 11) + tile * 32u + (m & 31u);
    else       src_row = tile * 128u + m;
    const size_t srow = (size_t)src_row * 2048;
    return (k < 2048u) ? (a + srow + k) : (b + srow + (k - 2048u));
}

DINLINE void chunk_store(__half* dstbuf, uint32_t t,
                         const float4& v0, const float4& v1)
{
    __half2 h0 = __floats2half2_rn(v0.x, v0.y);
    __half2 h1 = __floats2half2_rn(v0.z, v0.w);
    __half2 h2 = __floats2half2_rn(v1.x, v1.y);
    __half2 h3 = __floats2half2_rn(v1.z, v1.w);
    uint4 out;
    out.x = *reinterpret_cast<uint32_t*>(&h0);
    out.y = *reinterpret_cast<uint32_t*>(&h1);
    out.z = *reinterpret_cast<uint32_t*>(&h2);
    out.w = *reinterpret_cast<uint32_t*>(&h3);
    const uint32_t c = t & 7u, m = (t >> 3) & 127u;
    *reinterpret_cast<uint4*>((unsigned char*)dstbuf +
        ((size_t)(t >> 3) << 7) + ((c ^ (m & 7u)) << 4)) = out;
}

__global__ __launch_bounds__(256)
void cvt_pack(const float* __restrict__ x,  const float* __restrict__ h,
              const float* __restrict__ wi, const float* __restrict__ wh)
{
    const uint32_t g = blockIdx.x * 256u + threadIdx.x;
    float4 v[8];
    uint32_t t[4];

    if (g < (1u << 19)) {
        #pragma unroll
        for (int j = 0; j < 4; j++) t[j] = g + (uint32_t)j * (1u << 19);
        #pragma unroll
        for (int j = 0; j < 4; j++) {
            const float* s = chunk_src(x, h, t[j], 0);
            v[2*j]   = *reinterpret_cast<const float4*>(s);
            v[2*j+1] = *reinterpret_cast<const float4*>(s + 4);
        }
        #pragma unroll
        for (int j = 0; j < 4; j++) chunk_store(g_Ah, t[j], v[2*j], v[2*j+1]);
    } else {
        const uint32_t q = g - (1u << 19);
        #pragma unroll
        for (int j = 0; j < 4; j++) t[j] = q + (uint32_t)j * (1u << 20);
        #pragma unroll
        for (int j = 0; j < 4; j++) {
            const float* s = chunk_src(wi, wh, t[j], 1);
            v[2*j]   = *reinterpret_cast<const float4*>(s);
            v[2*j+1] = *reinterpret_cast<const float4*>(s + 4);
        }
        #pragma unroll
        for (int j = 0; j < 4; j++) chunk_store(g_Bh, t[j], v[2*j], v[2*j+1]);
    }
}

// ============================================================================
// Pass 2: fused GEMM + LSTM cell.
//   CTA tile 128(M) x 128(packed N = 4 gates x 32 h-cols), BK=64.
//   8 warps 2(M) x 4(N); warp tile 64x32; mma m16n8k16 fp16->fp32.
//   Pipeline: full[s] (tx mbarrier) + empty[s] (count-8, per-warp arrive).
//   Mainloop unrolled by ring depth: stage offsets/parities compile-time.
//   Producer round-robin: stage j refilled by warp j (lane 0).
// ============================================================================
static constexpr int TILE_BYTES  = 16384;                 // 128 x 128B
static constexpr int STAGE_BYTES = 2 * TILE_BYTES;        // A + B
static constexpr int STAGES      = 3;
static constexpr int KITERS      = 64;                    // 4096 / 64
static constexpr int SMEM_ALLOC  = STAGES * STAGE_BYTES + 1024;

__global__ __launch_bounds__(256, 2)
void lstm_gemm(const float* __restrict__ Bv, const float* __restrict__ Cin,
               float* __restrict__ Oh, float* __restrict__ Oc, float* __restrict__ Og)
{
    extern __shared__ unsigned char smraw[];
    __shared__ __align__(8) unsigned long long mbar_s[2 * STAGES];  // full[3], empty[3]
    __shared__ float s_bias[128];

    const int tid  = threadIdx.x;
    const int lane = tid & 31;
    const int w    = tid >> 5;
    const int wm   = w & 1;        // 0..1  (M)
    const int wn   = w >> 1;       // 0..3  (N)
    const int mtile = blockIdx.x & 31;   // 0..31
    const int ntile = blockIdx.x >> 5;   // 0..63 (h-col block of 32)

    const uint32_t smb = (smem_u32(smraw) + 1023u) & ~1023u;
    unsigned char* smal = smraw + (smb - smem_u32(smraw));
    const uint32_t mbb = smem_u32(&mbar_s[0]);     // full[s]  at mbb + s*8
    const uint32_t ebb = mbb + STAGES * 8;         // empty[s] at ebb + s*8

    if (tid == 0) {
        #pragma unroll
        for (int s = 0; s < STAGES; s++) {
            mbar_init(mbb + s * 8, 1);
            mbar_init(ebb + s * 8, 8);             // one arrive per warp
        }
    }
    if (tid < 128)
        s_bias[tid] = Bv[(size_t)((tid >> 5) << 11) + (size_t)ntile * 32 + (tid & 31)];
    __syncthreads();

    const uint64_t gA = (uint64_t)(const void*)g_Ah + (uint64_t)(mtile * 64) * TILE_BYTES;
    const uint64_t gB = (uint64_t)(const void*)g_Bh + (uint64_t)(ntile * 64) * TILE_BYTES;

    auto produce = [&](int it, int s) {
        const uint32_t mb = mbb + s * 8;
        mbar_expect(mb, (uint32_t)STAGE_BYTES);
        bulk_g2s(smb + s * STAGE_BYTES,
                 (const void*)(gA + (uint64_t)it * TILE_BYTES), TILE_BYTES, mb);
        bulk_g2s(smb + s * STAGE_BYTES + TILE_BYTES,
                 (const void*)(gB + (uint64_t)it * TILE_BYTES), TILE_BYTES, mb);
    };
    if (tid == 0) { produce(0, 0); produce(1, 1); produce(2, 2); }

    // fragment address components (byte offsets inside a 16KB tile)
    uint32_t arow[4], brow4[2], cxA[4], cxB[4];
    #pragma unroll
    for (int mi = 0; mi < 4; mi++)
        arow[mi] = (uint32_t)((wm * 64 + mi * 16 + ((lane >> 3) & 1) * 8 + (lane & 7)) << 7);
    #pragma unroll
    for (int p = 0; p < 2; p++)   // ldmatrix.x4 covering n-frag pair (2p, 2p+1)
        brow4[p] = (uint32_t)(TILE_BYTES +
                   ((wn * 32 + p * 16 + ((lane >> 4) & 1) * 8 + (lane & 7)) << 7));
    #pragma unroll
    for (int ks = 0; ks < 4; ks++) {
        cxA[ks] = (uint32_t)((((2 * ks + (lane >> 4)) ^ (lane & 7)) << 4));
        cxB[ks] = (uint32_t)((((2 * ks + ((lane >> 3) & 1)) ^ (lane & 7)) << 4));
    }

    float acc[4][4][4];
    #pragma unroll
    for (int mi = 0; mi < 4; mi++)
        #pragma unroll
        for (int ni = 0; ni < 4; ni++)
            #pragma unroll
            for (int r = 0; r < 4; r++) acc[mi][ni][r] = 0.0f;

    // one k-chunk consume: stage offsets are compile-time per call site
    auto consume = [&](uint32_t base) {
        #pragma unroll
        for (int ks = 0; ks < 4; ks++) {
            uint32_t b0[4], b1[4];
            #pragma unroll
            for (int p = 0; p < 2; p++)
                asm volatile("ldmatrix.sync.aligned.m8n8.x4.shared.b16 {%0,%1,%2,%3}, [%4];"
                             : "=r"(b0[2*p]), "=r"(b1[2*p]), "=r"(b0[2*p+1]), "=r"(b1[2*p+1])
                             : "r"(base + brow4[p] + cxB[ks]));
            #pragma unroll
            for (int mi = 0; mi < 4; mi++) {
                uint32_t a0, a1, a2, a3;
                asm volatile("ldmatrix.sync.aligned.m8n8.x4.shared.b16 {%0,%1,%2,%3}, [%4];"
                             : "=r"(a0), "=r"(a1), "=r"(a2), "=r"(a3)
                             : "r"(base + arow[mi] + cxA[ks]));
                #pragma unroll
                for (int ni = 0; ni < 4; ni++)
                    asm volatile(
                        "mma.sync.aligned.m16n8k16.row.col.f32.f16.f16.f32 "
                        "{%0,%1,%2,%3}, {%4,%5,%6,%7}, {%8,%9}, {%0,%1,%2,%3};"
                        : "+f"(acc[mi][ni][0]), "+f"(acc[mi][ni][1]),
                          "+f"(acc[mi][ni][2]), "+f"(acc[mi][ni][3])
                        : "r"(a0), "r"(a1), "r"(a2), "r"(a3),
                          "r"(b0[ni]), "r"(b1[ni]));
            }
        }
    };

    // ---- mainloop: 20 uniform trips of 3 (it 0..59), then 4-iter tail ----
    // Producer round-robin: stage j is refilled by warp j (lane 0), so each
    // producer warp blocks on the all-warps empty-wait only once per trip,
    // and the stalls land on three different SMSPs.
    for (int trip = 0; trip < 20; trip++) {
        const uint32_t par = (uint32_t)trip & 1u;
        const int it0 = trip * 3;
        #pragma unroll
        for (int j = 0; j < STAGES; j++) {          // stage j == it % 3
            mbar_wait(mbb + j * 8, par);
            consume(smb + j * STAGE_BYTES);
            if (lane == 0) mbar_arrive(ebb + j * 8);
            if (w == j && lane == 0) {
                mbar_wait(ebb + j * 8, par);
                produce(it0 + j + STAGES, j);       // it+3 <= 62 always
            }
        }
    }
    // tail: it = 60 (st0,p0), 61 (st1,p0), 62 (st2,p0), 63 (st0,p1)
    {
        mbar_wait(mbb + 0, 0);
        consume(smb);
        if (lane == 0) mbar_arrive(ebb + 0);
        if (w == 0 && lane == 0) { mbar_wait(ebb + 0, 0); produce(63, 0); }

        mbar_wait(mbb + 8, 0);
        consume(smb + STAGE_BYTES);
        if (lane == 0) mbar_arrive(ebb + 8);

        mbar_wait(mbb + 16, 0);
        consume(smb + 2 * STAGE_BYTES);
        if (lane == 0) mbar_arrive(ebb + 16);

        mbar_wait(mbb + 0, 1);
        consume(smb);
    }

    // ------------- fused epilogue: acc -> SMEM -> gates -> outputs ---------
    __syncthreads();                               // pipeline fully drained
    float* sC = reinterpret_cast<float*>(smal);    // [128][132] fp32

    const size_t mbase = (size_t)mtile * 128;
    const size_t hb    = (size_t)ntile * 32;

    // prefetch Cin (overlaps with acc->SMEM transpose + barrier)
    float cin[16];
    #pragma unroll
    for (int kk = 0; kk < 16; kk++) {
        const int idx = kk * 256 + tid;
        const int m = idx >> 5, cc = idx & 31;
        cin[kk] = Cin[(mbase + m) * 2048 + hb + cc];
    }

    #pragma unroll
    for (int mi = 0; mi < 4; mi++) {
        const int r0 = wm * 64 + mi * 16 + (lane >> 2);
        #pragma unroll
        for (int ni = 0; ni < 4; ni++) {
            const int c0 = wn * 32 + ni * 8 + (lane & 3) * 2;
            *reinterpret_cast<float2*>(&sC[r0 * 132 + c0]) =
                make_float2(acc[mi][ni][0], acc[mi][ni][1]);
            *reinterpret_cast<float2*>(&sC[(r0 + 8) * 132 + c0]) =
                make_float2(acc[mi][ni][2], acc[mi][ni][3]);
        }
    }
    __syncthreads();

    #pragma unroll
    for (int kk = 0; kk < 16; kk++) {
        const int idx = kk * 256 + tid;
        const int m = idx >> 5, cc = idx & 31;
        const float gf = sC[m * 132 +       cc] + s_bias[cc];
        const float gi = sC[m * 132 +  32 + cc] + s_bias[32 + cc];
        const float gs = sC[m * 132 +  64 + cc] + s_bias[64 + cc];
        const float gg = sC[m * 132 +  96 + cc] + s_bias[96 + cc];

        const float f  = sigf(gf);
        const float ii = sigf(gi);
        const float ss = tanhp(gs);
        const float oo = sigf(gg);
        const float cn = f * cin[kk] + ii * ss;
        const float hn = oo * tanhp(cn);

        const size_t off = (mbase + m) * 2048 + hb + cc;
        Oh[off] = hn;
        Oc[off] = cn;
        Og[off] = oo;
    }
}

// ============================================================================
// launch
// ============================================================================
extern "C" void kernel_launch(void* const* d_in, const int* in_sizes, int n_in,
                              void* d_out, int out_size)
{
    const float* x    = (const float*)d_in[0];
    const float* h    = (const float*)d_in[1];
    const float* c    = (const float*)d_in[2];
    /* d_in[3] = o, unused by the reference computation */
    const float* w_ih = (const float*)d_in[4];
    const float* w_hh = (const float*)d_in[5];
    const float* b    = (const float*)d_in[6];
    float* out = (float*)d_out;

    cudaFuncSetAttribute(lstm_gemm,
                         cudaFuncAttributeMaxDynamicSharedMemorySize, SMEM_ALLOC);

    cvt_pack<<<6144, 256>>>(x, h, w_ih, w_hh);

    float* out_h  = out;
    float* out_c  = out + (size_t)4096 * 2048;
    float* out_go = out + (size_t)2 * 4096 * 2048;
    lstm_gemm<<<2048, 256, SMEM_ALLOC>>>(b, c, out_h, out_c, out_go);
}

// round 12
// speedup vs baseline: 1.7652x; 1.0040x over previous
#include <cuda_runtime.h>
#include <cuda_fp16.h>
#include <cstdint>

// ============================================================================
// LSTMCell for GB300 — sm_103 (non-'a') path: fp16 mma.sync + cp.async.bulk.
//
//   Pass 1: fp32 -> fp16 (RN), pre-tiled + SW128-swizzled, MLP=8 loads.
//   Pass 2: GEMM 128x128x(BK=64), 3-stage bulk-copy mbarrier ring with
//           trip-level unroll (compile-time stage offsets/parities) and
//           round-robin producer (stage j refilled by warp j, lane 0),
//           fused fast-math LSTM epilogue, fully float4-vectorized.
// ============================================================================

#define DINLINE __device__ __forceinline__

__device__ __align__(1024) __half g_Ah[4096UL * 4096];   // 32 MB
__device__ __align__(1024) __half g_Bh[8192UL * 4096];   // 64 MB

// ------------------------------- helpers -----------------------------------
DINLINE uint32_t smem_u32(const void* p) {
    uint32_t a;
    asm("{ .reg .u64 t; cvta.to.shared.u64 t, %1; cvt.u32.u64 %0, t; }"
        : "=r"(a) : "l"(p));
    return a;
}

DINLINE void mbar_init(uint32_t a, uint32_t cnt) {
    asm volatile("mbarrier.init.shared.b64 [%0], %1;" :: "r"(a), "r"(cnt) : "memory");
}
DINLINE void mbar_expect(uint32_t a, uint32_t tx) {
    asm volatile("mbarrier.arrive.expect_tx.shared.b64 _, [%0], %1;"
                 :: "r"(a), "r"(tx) : "memory");
}
DINLINE void mbar_arrive(uint32_t a) {
    asm volatile("mbarrier.arrive.shared.b64 _, [%0];" :: "r"(a) : "memory");
}
DINLINE void mbar_wait(uint32_t mbar, uint32_t parity) {
    uint32_t done;
    asm volatile(
        "{\n .reg .pred p;\n"
        " mbarrier.try_wait.parity.acquire.cta.shared::cta.b64 p, [%1], %2;\n"
        " selp.b32 %0, 1, 0, p;\n}"
        : "=r"(done) : "r"(mbar), "r"(parity) : "memory");
    if (!done) {
        asm volatile(
            "{\n .reg .pred P1;\n"
            "WL%=:\n"
            " mbarrier.try_wait.parity.acquire.cta.shared::cta.b64 P1, [%0], %1, 0x989680;\n"
            " @P1 bra.uni WD%=;\n"
            " bra.uni WL%=;\n"
            "WD%=:\n}"
            :: "r"(mbar), "r"(parity) : "memory");
    }
}

DINLINE void bulk_g2s(uint32_t dst, const void* src, uint32_t bytes, uint32_t mbar) {
    asm volatile(
        "cp.async.bulk.shared::cluster.global.mbarrier::complete_tx::bytes [%0], [%1], %2, [%3];"
        :: "r"(dst), "l"(src), "r"(bytes), "r"(mbar) : "memory");
}

// fast-math gates (ex2/rcp approx; errors ~1e-7, negligible vs fp16 inputs)
DINLINE float ex2a(float x) { float y; asm("ex2.approx.f32 %0, %1;" : "=f"(y) : "f"(x)); return y; }
DINLINE float rcpa(float x) { float y; asm("rcp.approx.f32 %0, %1;" : "=f"(y) : "f"(x)); return y; }
DINLINE float sigf(float x)  { return rcpa(1.0f + ex2a(-1.442695041f * x)); }
DINLINE float tanhp(float x) { return 2.0f * sigf(2.0f * x) - 1.0f; }

// ============================================================================
// Pass 1: convert + tile + swizzle.  Chunk = 16B of fp16 (8 halves).
//   chunk id bits: [c:3][m:7][kc:6][tile:rest]
//   4 chunks per thread, all 8 LDG.128 issued before converts (MLP=8).
// ============================================================================
DINLINE const float* chunk_src(const float* a, const float* b,
                               uint32_t t, int which)
{
    const uint32_t c = t & 7u;
    const uint32_t m = (t >> 3) & 127u;
    const uint32_t k = ((t >> 10) & 63u) * 64u + c * 8u;
    const uint32_t tile = t >> 16;
    uint32_t src_row;
    if (which) src_row = ((m >> 5) << 11) + tile * 32u + (m & 31u);
    else       src_row = tile * 128u + m;
    const size_t srow = (size_t)src_row * 2048;
    return (k < 2048u) ? (a + srow + k) : (b + srow + (k - 2048u));
}

DINLINE void chunk_store(__half* dstbuf, uint32_t t,
                         const float4& v0, const float4& v1)
{
    __half2 h0 = __floats2half2_rn(v0.x, v0.y);
    __half2 h1 = __floats2half2_rn(v0.z, v0.w);
    __half2 h2 = __floats2half2_rn(v1.x, v1.y);
    __half2 h3 = __floats2half2_rn(v1.z, v1.w);
    uint4 out;
    out.x = *reinterpret_cast<uint32_t*>(&h0);
    out.y = *reinterpret_cast<uint32_t*>(&h1);
    out.z = *reinterpret_cast<uint32_t*>(&h2);
    out.w = *reinterpret_cast<uint32_t*>(&h3);
    const uint32_t c = t & 7u, m = (t >> 3) & 127u;
    *reinterpret_cast<uint4*>((unsigned char*)dstbuf +
        ((size_t)(t >> 3) << 7) + ((c ^ (m & 7u)) << 4)) = out;
}

__global__ __launch_bounds__(256)
void cvt_pack(const float* __restrict__ x,  const float* __restrict__ h,
              const float* __restrict__ wi, const float* __restrict__ wh)
{
    const uint32_t g = blockIdx.x * 256u + threadIdx.x;
    float4 v[8];
    uint32_t t[4];

    if (g < (1u << 19)) {
        #pragma unroll
        for (int j = 0; j < 4; j++) t[j] = g + (uint32_t)j * (1u << 19);
        #pragma unroll
        for (int j = 0; j < 4; j++) {
            const float* s = chunk_src(x, h, t[j], 0);
            v[2*j]   = *reinterpret_cast<const float4*>(s);
            v[2*j+1] = *reinterpret_cast<const float4*>(s + 4);
        }
        #pragma unroll
        for (int j = 0; j < 4; j++) chunk_store(g_Ah, t[j], v[2*j], v[2*j+1]);
    } else {
        const uint32_t q = g - (1u << 19);
        #pragma unroll
        for (int j = 0; j < 4; j++) t[j] = q + (uint32_t)j * (1u << 20);
        #pragma unroll
        for (int j = 0; j < 4; j++) {
            const float* s = chunk_src(wi, wh, t[j], 1);
            v[2*j]   = *reinterpret_cast<const float4*>(s);
            v[2*j+1] = *reinterpret_cast<const float4*>(s + 4);
        }
        #pragma unroll
        for (int j = 0; j < 4; j++) chunk_store(g_Bh, t[j], v[2*j], v[2*j+1]);
    }
}

// ============================================================================
// Pass 2: fused GEMM + LSTM cell.
//   CTA tile 128(M) x 128(packed N = 4 gates x 32 h-cols), BK=64.
//   8 warps 2(M) x 4(N); warp tile 64x32; mma m16n8k16 fp16->fp32.
//   Pipeline: full[s] (tx mbarrier) + empty[s] (count-8, per-warp arrive).
//   Mainloop unrolled by ring depth; producer round-robin (warp j, stage j).
// ============================================================================
static constexpr int TILE_BYTES  = 16384;                 // 128 x 128B
static constexpr int STAGE_BYTES = 2 * TILE_BYTES;        // A + B
static constexpr int STAGES      = 3;
static constexpr int KITERS      = 64;                    // 4096 / 64
static constexpr int SMEM_ALLOC  = STAGES * STAGE_BYTES + 1024;

__global__ __launch_bounds__(256, 2)
void lstm_gemm(const float* __restrict__ Bv, const float* __restrict__ Cin,
               float* __restrict__ Oh, float* __restrict__ Oc, float* __restrict__ Og)
{
    extern __shared__ unsigned char smraw[];
    __shared__ __align__(8) unsigned long long mbar_s[2 * STAGES];  // full[3], empty[3]
    __shared__ float s_bias[128];

    const int tid  = threadIdx.x;
    const int lane = tid & 31;
    const int w    = tid >> 5;
    const int wm   = w & 1;        // 0..1  (M)
    const int wn   = w >> 1;       // 0..3  (N)
    const int mtile = blockIdx.x & 31;   // 0..31
    const int ntile = blockIdx.x >> 5;   // 0..63 (h-col block of 32)

    const uint32_t smb = (smem_u32(smraw) + 1023u) & ~1023u;
    unsigned char* smal = smraw + (smb - smem_u32(smraw));
    const uint32_t mbb = smem_u32(&mbar_s[0]);     // full[s]  at mbb + s*8
    const uint32_t ebb = mbb + STAGES * 8;         // empty[s] at ebb + s*8

    if (tid == 0) {
        #pragma unroll
        for (int s = 0; s < STAGES; s++) {
            mbar_init(mbb + s * 8, 1);
            mbar_init(ebb + s * 8, 8);             // one arrive per warp
        }
    }
    if (tid < 128)
        s_bias[tid] = Bv[(size_t)((tid >> 5) << 11) + (size_t)ntile * 32 + (tid & 31)];
    __syncthreads();

    const uint64_t gA = (uint64_t)(const void*)g_Ah + (uint64_t)(mtile * 64) * TILE_BYTES;
    const uint64_t gB = (uint64_t)(const void*)g_Bh + (uint64_t)(ntile * 64) * TILE_BYTES;

    auto produce = [&](int it, int s) {
        const uint32_t mb = mbb + s * 8;
        mbar_expect(mb, (uint32_t)STAGE_BYTES);
        bulk_g2s(smb + s * STAGE_BYTES,
                 (const void*)(gA + (uint64_t)it * TILE_BYTES), TILE_BYTES, mb);
        bulk_g2s(smb + s * STAGE_BYTES + TILE_BYTES,
                 (const void*)(gB + (uint64_t)it * TILE_BYTES), TILE_BYTES, mb);
    };
    if (tid == 0) { produce(0, 0); produce(1, 1); produce(2, 2); }

    // fragment address components (byte offsets inside a 16KB tile)
    uint32_t arow[4], brow4[2], cxA[4], cxB[4];
    #pragma unroll
    for (int mi = 0; mi < 4; mi++)
        arow[mi] = (uint32_t)((wm * 64 + mi * 16 + ((lane >> 3) & 1) * 8 + (lane & 7)) << 7);
    #pragma unroll
    for (int p = 0; p < 2; p++)   // ldmatrix.x4 covering n-frag pair (2p, 2p+1)
        brow4[p] = (uint32_t)(TILE_BYTES +
                   ((wn * 32 + p * 16 + ((lane >> 4) & 1) * 8 + (lane & 7)) << 7));
    #pragma unroll
    for (int ks = 0; ks < 4; ks++) {
        cxA[ks] = (uint32_t)((((2 * ks + (lane >> 4)) ^ (lane & 7)) << 4));
        cxB[ks] = (uint32_t)((((2 * ks + ((lane >> 3) & 1)) ^ (lane & 7)) << 4));
    }

    float acc[4][4][4];
    #pragma unroll
    for (int mi = 0; mi < 4; mi++)
        #pragma unroll
        for (int ni = 0; ni < 4; ni++)
            #pragma unroll
            for (int r = 0; r < 4; r++) acc[mi][ni][r] = 0.0f;

    // one k-chunk consume: stage offsets are compile-time per call site
    auto consume = [&](uint32_t base) {
        #pragma unroll
        for (int ks = 0; ks < 4; ks++) {
            uint32_t b0[4], b1[4];
            #pragma unroll
            for (int p = 0; p < 2; p++)
                asm volatile("ldmatrix.sync.aligned.m8n8.x4.shared.b16 {%0,%1,%2,%3}, [%4];"
                             : "=r"(b0[2*p]), "=r"(b1[2*p]), "=r"(b0[2*p+1]), "=r"(b1[2*p+1])
                             : "r"(base + brow4[p] + cxB[ks]));
            #pragma unroll
            for (int mi = 0; mi < 4; mi++) {
                uint32_t a0, a1, a2, a3;
                asm volatile("ldmatrix.sync.aligned.m8n8.x4.shared.b16 {%0,%1,%2,%3}, [%4];"
                             : "=r"(a0), "=r"(a1), "=r"(a2), "=r"(a3)
                             : "r"(base + arow[mi] + cxA[ks]));
                #pragma unroll
                for (int ni = 0; ni < 4; ni++)
                    asm volatile(
                        "mma.sync.aligned.m16n8k16.row.col.f32.f16.f16.f32 "
                        "{%0,%1,%2,%3}, {%4,%5,%6,%7}, {%8,%9}, {%0,%1,%2,%3};"
                        : "+f"(acc[mi][ni][0]), "+f"(acc[mi][ni][1]),
                          "+f"(acc[mi][ni][2]), "+f"(acc[mi][ni][3])
                        : "r"(a0), "r"(a1), "r"(a2), "r"(a3),
                          "r"(b0[ni]), "r"(b1[ni]));
            }
        }
    };

    // ---- mainloop: 20 uniform trips of 3 (it 0..59), then 4-iter tail ----
    for (int trip = 0; trip < 20; trip++) {
        const uint32_t par = (uint32_t)trip & 1u;
        const int it0 = trip * 3;
        #pragma unroll
        for (int j = 0; j < STAGES; j++) {          // stage j == it % 3
            mbar_wait(mbb + j * 8, par);
            consume(smb + j * STAGE_BYTES);
            if (lane == 0) mbar_arrive(ebb + j * 8);
            if (w == j && lane == 0) {
                mbar_wait(ebb + j * 8, par);
                produce(it0 + j + STAGES, j);       // it+3 <= 62 always
            }
        }
    }
    // tail: it = 60 (st0,p0), 61 (st1,p0), 62 (st2,p0), 63 (st0,p1)
    {
        mbar_wait(mbb + 0, 0);
        consume(smb);
        if (lane == 0) mbar_arrive(ebb + 0);
        if (w == 0 && lane == 0) { mbar_wait(ebb + 0, 0); produce(63, 0); }

        mbar_wait(mbb + 8, 0);
        consume(smb + STAGE_BYTES);
        if (lane == 0) mbar_arrive(ebb + 8);

        mbar_wait(mbb + 16, 0);
        consume(smb + 2 * STAGE_BYTES);
        if (lane == 0) mbar_arrive(ebb + 16);

        mbar_wait(mbb + 0, 1);
        consume(smb);
    }

    // ------------- fused epilogue: acc -> SMEM -> gates -> outputs ---------
    // Fully float4-vectorized: 4 kk-iterations, LDS.128/LDG.128/STG.128.
    __syncthreads();                               // pipeline fully drained
    float* sC = reinterpret_cast<float*>(smal);    // [128][132] fp32

    const size_t mbase = (size_t)mtile * 128;
    const size_t hb    = (size_t)ntile * 32;

    // prefetch Cin as float4 (overlaps with acc->SMEM transpose + barrier)
    float4 cin4[4];
    #pragma unroll
    for (int kk = 0; kk < 4; kk++) {
        const int idx = kk * 256 + tid;
        const int m = idx >> 3, c4 = (idx & 7) * 4;
        cin4[kk] = *reinterpret_cast<const float4*>(&Cin[(mbase + m) * 2048 + hb + c4]);
    }

    #pragma unroll
    for (int mi = 0; mi < 4; mi++) {
        const int r0 = wm * 64 + mi * 16 + (lane >> 2);
        #pragma unroll
        for (int ni = 0; ni < 4; ni++) {
            const int c0 = wn * 32 + ni * 8 + (lane & 3) * 2;
            *reinterpret_cast<float2*>(&sC[r0 * 132 + c0]) =
                make_float2(acc[mi][ni][0], acc[mi][ni][1]);
            *reinterpret_cast<float2*>(&sC[(r0 + 8) * 132 + c0]) =
                make_float2(acc[mi][ni][2], acc[mi][ni][3]);
        }
    }
    __syncthreads();

    #pragma unroll
    for (int kk = 0; kk < 4; kk++) {
        const int idx = kk * 256 + tid;
        const int m = idx >> 3, c4 = (idx & 7) * 4;
        const float* row = &sC[m * 132 + c4];

        const float4 gf = *reinterpret_cast<const float4*>(row);
        const float4 gi = *reinterpret_cast<const float4*>(row + 32);
        const float4 gs = *reinterpret_cast<const float4*>(row + 64);
        const float4 gg = *reinterpret_cast<const float4*>(row + 96);
        const float4 bf = *reinterpret_cast<const float4*>(&s_bias[c4]);
        const float4 bi = *reinterpret_cast<const float4*>(&s_bias[32 + c4]);
        const float4 bs = *reinterpret_cast<const float4*>(&s_bias[64 + c4]);
        const float4 bo = *reinterpret_cast<const float4*>(&s_bias[96 + c4]);
        const float4 cc = cin4[kk];

        float4 hn, cn, oo;
        {
            const float f = sigf(gf.x + bf.x), i = sigf(gi.x + bi.x);
            const float s = tanhp(gs.x + bs.x), o = sigf(gg.x + bo.x);
            cn.x = f * cc.x + i * s; hn.x = o * tanhp(cn.x); oo.x = o;
        }
        {
            const float f = sigf(gf.y + bf.y), i = sigf(gi.y + bi.y);
            const float s = tanhp(gs.y + bs.y), o = sigf(gg.y + bo.y);
            cn.y = f * cc.y + i * s; hn.y = o * tanhp(cn.y); oo.y = o;
        }
        {
            const float f = sigf(gf.z + bf.z), i = sigf(gi.z + bi.z);
            const float s = tanhp(gs.z + bs.z), o = sigf(gg.z + bo.z);
            cn.z = f * cc.z + i * s; hn.z = o * tanhp(cn.z); oo.z = o;
        }
        {
            const float f = sigf(gf.w + bf.w), i = sigf(gi.w + bi.w);
            const float s = tanhp(gs.w + bs.w), o = sigf(gg.w + bo.w);
            cn.w = f * cc.w + i * s; hn.w = o * tanhp(cn.w); oo.w = o;
        }

        const size_t off = (mbase + m) * 2048 + hb + c4;
        *reinterpret_cast<float4*>(&Oh[off]) = hn;
        *reinterpret_cast<float4*>(&Oc[off]) = cn;
        *reinterpret_cast<float4*>(&Og[off]) = oo;
    }
}

// ============================================================================
// launch
// ============================================================================
extern "C" void kernel_launch(void* const* d_in, const int* in_sizes, int n_in,
                              void* d_out, int out_size)
{
    const float* x    = (const float*)d_in[0];
    const float* h    = (const float*)d_in[1];
    const float* c    = (const float*)d_in[2];
    /* d_in[3] = o, unused by the reference computation */
    const float* w_ih = (const float*)d_in[4];
    const float* w_hh = (const float*)d_in[5];
    const float* b    = (const float*)d_in[6];
    float* out = (float*)d_out;

    cudaFuncSetAttribute(lstm_gemm,
                         cudaFuncAttributeMaxDynamicSharedMemorySize, SMEM_ALLOC);

    cvt_pack<<<6144, 256>>>(x, h, w_ih, w_hh);

    float* out_h  = out;
    float* out_c  = out + (size_t)4096 * 2048;
    float* out_go = out + (size_t)2 * 4096 * 2048;
    lstm_gemm<<<2048, 256, SMEM_ALLOC>>>(b, c, out_h, out_c, out_go);
}